// round 4
// baseline (speedup 1.0000x reference)
#include <cuda_runtime.h>

#define S 2048
#define C 4096
#define K 4
#define SCHUNK 8            // samples per block
#define TILE 1032           // 1024 channels + 4 halo each side
#define BLKCH 1024          // channels per block

// Per-sample precomputed params: tap weights and byte offset r*4 (r = mi+4 in [0,7])
__device__ float4 g_w0[S];
__device__ float4 g_w1[S];
__device__ int4   g_rb[S];

__global__ void prep_kernel(const float* __restrict__ contrib,
                            const float* __restrict__ shift)
{
    const int s = blockIdx.x * blockDim.x + threadIdx.x;
    if (s >= S) return;
    const float4 sh = *reinterpret_cast<const float4*>(shift + s * K);
    const float4 w  = *reinterpret_cast<const float4*>(contrib + s * K);
    float shs[4] = {sh.x, sh.y, sh.z, sh.w};
    float ws[4]  = {w.x,  w.y,  w.z,  w.w};
    float w0v[4], w1v[4]; int rb[4];
#pragma unroll
    for (int k = 0; k < K; k++) {
        float m = floorf(shs[k]);
        float f = shs[k] - m;
        int  mi = (int)m;
        mi = max(-4, min(3, mi));        // shift in [-4,4) -> mi in [-4,3]
        w1v[k] = ws[k] * f;
        w0v[k] = ws[k] - w1v[k];
        rb[k]  = (mi + 4) * 4;           // byte offset into halo'd tile
    }
    g_w0[s] = make_float4(w0v[0], w0v[1], w0v[2], w0v[3]);
    g_w1[s] = make_float4(w1v[0], w1v[1], w1v[2], w1v[3]);
    g_rb[s] = make_int4(rb[0], rb[1], rb[2], rb[3]);
}

// Block: 256 threads, 1024 channels [B0, B0+1024), SCHUNK samples.
// Warp w owns channels [B0+128w, B0+128w+128); lane handles 4 channels at
// stride 32 (c = base + 32j + lane) so tap LDS is lane-consecutive (conflict-free).
__global__ void __launch_bounds__(256, 8)
smf_kernel(const float* __restrict__ comp,   // (K, C)
           float* __restrict__ out)          // (S, C)
{
    __shared__ float tile[K * TILE];

    const int tid  = threadIdx.x;
    const int warp = tid >> 5;
    const int lane = tid & 31;
    const int B0   = blockIdx.x * BLKCH;
    const int s0   = blockIdx.y * SCHUNK;

    // Stage components tile (+halo, zero-padded at global edges)
#pragma unroll
    for (int k = 0; k < K; k++) {
        for (int t = tid; t < TILE; t += 256) {
            const int g = B0 - 4 + t;
            tile[k * TILE + t] = (g >= 0 && g < C) ? __ldg(&comp[k * C + g]) : 0.f;
        }
    }
    __syncthreads();

    // Per-thread smem byte base: tile[warp*128 + lane] (j and k folded into imm offsets)
    const float* tbase = &tile[warp * 128 + lane];

    float* op = out + (size_t)s0 * C + B0 + warp * 128 + lane;

    for (int s = s0; s < s0 + SCHUNK; s++) {
        const float4 w0 = __ldg(&g_w0[s]);
        const float4 w1 = __ldg(&g_w1[s]);
        const int4   rb = __ldg(&g_rb[s]);

        float a0 = 0.f, a1 = 0.f, a2 = 0.f, a3 = 0.f;

#pragma unroll
        for (int k = 0; k < K; k++) {
            const float W0 = (k == 0) ? w0.x : (k == 1) ? w0.y : (k == 2) ? w0.z : w0.w;
            const float W1 = (k == 0) ? w1.x : (k == 1) ? w1.y : (k == 2) ? w1.z : w1.w;
            const int   R  = (k == 0) ? rb.x : (k == 1) ? rb.y : (k == 2) ? rb.z : rb.w;

            // tap pointer: tbase + k*TILE + r  (r in elements = R/4)
            const float* tp = reinterpret_cast<const float*>(
                reinterpret_cast<const char*>(tbase + k * TILE) + R);

            const float h00 = tp[0];        // j=0 taps
            const float h01 = tp[1];
            const float h10 = tp[32];       // j=1
            const float h11 = tp[33];
            const float h20 = tp[64];       // j=2
            const float h21 = tp[65];
            const float h30 = tp[96];       // j=3
            const float h31 = tp[97];

            a0 = fmaf(W0, h00, fmaf(W1, h01, a0));
            a1 = fmaf(W0, h10, fmaf(W1, h11, a1));
            a2 = fmaf(W0, h20, fmaf(W1, h21, a2));
            a3 = fmaf(W0, h30, fmaf(W1, h31, a3));
        }

        op[0]  = a0;
        op[32] = a1;
        op[64] = a2;
        op[96] = a3;
        op += C;
    }
}

extern "C" void kernel_launch(void* const* d_in, const int* in_sizes, int n_in,
                              void* d_out, int out_size) {
    // metadata order: inputs (unused), components, contributions, shift
    const float* comp    = (const float*)d_in[1];
    const float* contrib = (const float*)d_in[2];
    const float* shift   = (const float*)d_in[3];
    float*       out     = (float*)d_out;

    prep_kernel<<<(S + 255) / 256, 256>>>(contrib, shift);

    dim3 grid(C / BLKCH, S / SCHUNK);   // (4, 256) = 1024 blocks
    smf_kernel<<<grid, 256>>>(comp, out);
}

// round 5
// speedup vs baseline: 1.2162x; 1.2162x over previous
#include <cuda_runtime.h>

#define S 2048
#define C 4096
#define K 4
#define SCHUNK 16           // samples per block
#define BLKCH 1024          // channels per block (256 thr * 4 ch)
#define TILEW 1032          // logical tile words per component (1024 + 4 halo each side)
#define SUB 264             // de-interleave sub-array stride (words), >= 258
#define KSTR (4 * SUB)      // physical words per component tile (1056)

// Per-sample precomputed params (in shared memory, computed in-block).
struct SParams {
    float4 w0;        // tap0 weight per k
    float4 w1;        // tap1 weight per k
    int4   off[K];    // byte offsets f(r+j)*4, j=0..3  (j=4 is off.x + 4)
};

// Thread owns channels B0 + 4*tid .. +3 (consecutive -> STG.128).
// Tile word t (channel B0-4+t) stored at phys = (t&3)*SUB + (t>>2), so the
// tap word 4*tid + r + j sits at [tid + f(r+j)]: lane-consecutive LDS,
// conflict-free, with a sample-uniform precomputed offset. f(x)=(x&3)*SUB+(x>>2).
__global__ void __launch_bounds__(256, 4)
smf_kernel(const float* __restrict__ comp,      // (K, C)
           const float* __restrict__ contrib,   // (S, K)
           const float* __restrict__ shift,     // (S, K)
           float* __restrict__ out)             // (S, C)
{
    __shared__ float   tile[K * KSTR];
    __shared__ SParams prm[SCHUNK];

    const int tid = threadIdx.x;
    const int B0  = blockIdx.x * BLKCH;
    const int s0  = blockIdx.y * SCHUNK;

    // ---- in-block param computation: thread tid<64 handles one (sample, k) ----
    if (tid < SCHUNK * K) {
        const int sl = tid >> 2;
        const int k  = tid & 3;
        const int s  = s0 + sl;
        const float sh = __ldg(&shift[s * K + k]);
        const float w  = __ldg(&contrib[s * K + k]);
        const float m  = floorf(sh);
        const float f  = sh - m;
        int r = (int)m + 4;                 // shift in [-4,4) -> r in [0,7]
        r = max(0, min(7, r));
        const float w1 = w * f;
        reinterpret_cast<float*>(&prm[sl].w0)[k] = w - w1;
        reinterpret_cast<float*>(&prm[sl].w1)[k] = w1;
        int o[4];
#pragma unroll
        for (int j = 0; j < 4; j++) {
            const int x = r + j;
            o[j] = ((x & 3) * SUB + (x >> 2)) * 4;   // byte offset
        }
        prm[sl].off[k] = make_int4(o[0], o[1], o[2], o[3]);
    }

    // ---- stage component tile (de-interleaved by t&3, zero-padded halo) ----
#pragma unroll
    for (int k = 0; k < K; k++) {
        for (int t = tid; t < TILEW; t += 256) {
            const int g = B0 - 4 + t;
            const float v = (g >= 0 && g < C) ? __ldg(&comp[k * C + g]) : 0.f;
            tile[k * KSTR + (t & 3) * SUB + (t >> 2)] = v;
        }
    }
    __syncthreads();

    // per-k tap base pointers (byte-addressed), hoisted out of the sample loop
    const char* tb0 = reinterpret_cast<const char*>(&tile[0 * KSTR + tid]);
    const char* tb1 = reinterpret_cast<const char*>(&tile[1 * KSTR + tid]);
    const char* tb2 = reinterpret_cast<const char*>(&tile[2 * KSTR + tid]);
    const char* tb3 = reinterpret_cast<const char*>(&tile[3 * KSTR + tid]);

    float* op = out + (size_t)s0 * C + B0 + 4 * tid;

#pragma unroll 2
    for (int sl = 0; sl < SCHUNK; sl++) {
        const float4 W0 = prm[sl].w0;       // broadcast LDS.128
        const float4 W1 = prm[sl].w1;

        float a0 = 0.f, a1 = 0.f, a2 = 0.f, a3 = 0.f;

#pragma unroll
        for (int k = 0; k < K; k++) {
            const int4 off = prm[sl].off[k];  // broadcast LDS.128
            const char* tb = (k == 0) ? tb0 : (k == 1) ? tb1 : (k == 2) ? tb2 : tb3;
            const float w0 = (k == 0) ? W0.x : (k == 1) ? W0.y : (k == 2) ? W0.z : W0.w;
            const float w1 = (k == 0) ? W1.x : (k == 1) ? W1.y : (k == 2) ? W1.z : W1.w;

            const float h0 = *reinterpret_cast<const float*>(tb + off.x);
            const float h1 = *reinterpret_cast<const float*>(tb + off.y);
            const float h2 = *reinterpret_cast<const float*>(tb + off.z);
            const float h3 = *reinterpret_cast<const float*>(tb + off.w);
            const float h4 = *reinterpret_cast<const float*>(tb + off.x + 4); // f(r+4)=f(r)+1 word

            a0 = fmaf(w0, h0, fmaf(w1, h1, a0));
            a1 = fmaf(w0, h1, fmaf(w1, h2, a1));
            a2 = fmaf(w0, h2, fmaf(w1, h3, a2));
            a3 = fmaf(w0, h3, fmaf(w1, h4, a3));
        }

        *reinterpret_cast<float4*>(op) = make_float4(a0, a1, a2, a3);
        op += C;
    }
}

extern "C" void kernel_launch(void* const* d_in, const int* in_sizes, int n_in,
                              void* d_out, int out_size) {
    // metadata order: inputs (unused), components, contributions, shift
    const float* comp    = (const float*)d_in[1];
    const float* contrib = (const float*)d_in[2];
    const float* shift   = (const float*)d_in[3];
    float*       out     = (float*)d_out;

    dim3 grid(C / BLKCH, S / SCHUNK);   // (4, 128) = 512 blocks
    smf_kernel<<<grid, 256>>>(comp, contrib, shift, out);
}

// round 6
// speedup vs baseline: 1.3636x; 1.1212x over previous
#include <cuda_runtime.h>

#define S 2048
#define C 4096
#define K 4
#define SCHUNK 8            // samples per block (halved: more blocks -> more resident warps)
#define BLKCH 1024          // channels per block (256 thr * 4 ch)
#define TILEW 1032          // logical tile words per component (1024 + 4 halo each side)
#define SUB 264             // de-interleave sub-array stride (words), >= 258
#define KSTR (4 * SUB)      // physical words per component tile (1056)

// Per-sample precomputed params (in shared memory, computed in-block).
struct SParams {
    float4 w0;        // tap0 weight per k
    float4 w1;        // tap1 weight per k
    int4   off[K];    // byte offsets f(r+j)*4, j=0..3  (j=4 is off.x + 4)
};

// Thread owns channels B0 + 4*tid .. +3 (consecutive -> STG.128).
// Tile word t (channel B0-4+t) stored at phys = (t&3)*SUB + (t>>2), so the
// tap word 4*tid + r + j sits at [tid + f(r+j)]: lane-consecutive LDS,
// conflict-free, with a sample-uniform precomputed offset. f(x)=(x&3)*SUB+(x>>2).
__global__ void __launch_bounds__(256, 8)
smf_kernel(const float* __restrict__ comp,      // (K, C)
           const float* __restrict__ contrib,   // (S, K)
           const float* __restrict__ shift,     // (S, K)
           float* __restrict__ out)             // (S, C)
{
    __shared__ float   tile[K * KSTR];
    __shared__ SParams prm[SCHUNK];

    const int tid = threadIdx.x;
    const int B0  = blockIdx.x * BLKCH;
    const int s0  = blockIdx.y * SCHUNK;

    // ---- in-block param computation: thread tid<32 handles one (sample, k) ----
    if (tid < SCHUNK * K) {
        const int sl = tid >> 2;
        const int k  = tid & 3;
        const int s  = s0 + sl;
        const float sh = __ldg(&shift[s * K + k]);
        const float w  = __ldg(&contrib[s * K + k]);
        const float m  = floorf(sh);
        const float f  = sh - m;
        int r = (int)m + 4;                 // shift in [-4,4) -> r in [0,7]
        r = max(0, min(7, r));
        const float w1 = w * f;
        reinterpret_cast<float*>(&prm[sl].w0)[k] = w - w1;
        reinterpret_cast<float*>(&prm[sl].w1)[k] = w1;
        int o[4];
#pragma unroll
        for (int j = 0; j < 4; j++) {
            const int x = r + j;
            o[j] = ((x & 3) * SUB + (x >> 2)) * 4;   // byte offset
        }
        prm[sl].off[k] = make_int4(o[0], o[1], o[2], o[3]);
    }

    // ---- stage component tile (de-interleaved by t&3, zero-padded halo) ----
#pragma unroll
    for (int k = 0; k < K; k++) {
        for (int t = tid; t < TILEW; t += 256) {
            const int g = B0 - 4 + t;
            const float v = (g >= 0 && g < C) ? __ldg(&comp[k * C + g]) : 0.f;
            tile[k * KSTR + (t & 3) * SUB + (t >> 2)] = v;
        }
    }
    __syncthreads();

    // per-k tap base pointers (byte-addressed), hoisted out of the sample loop
    const char* tb0 = reinterpret_cast<const char*>(&tile[0 * KSTR + tid]);
    const char* tb1 = reinterpret_cast<const char*>(&tile[1 * KSTR + tid]);
    const char* tb2 = reinterpret_cast<const char*>(&tile[2 * KSTR + tid]);
    const char* tb3 = reinterpret_cast<const char*>(&tile[3 * KSTR + tid]);

    float* op = out + (size_t)s0 * C + B0 + 4 * tid;

#pragma unroll 2
    for (int sl = 0; sl < SCHUNK; sl++) {
        const float4 W0 = prm[sl].w0;       // broadcast LDS.128
        const float4 W1 = prm[sl].w1;

        float a0 = 0.f, a1 = 0.f, a2 = 0.f, a3 = 0.f;

#pragma unroll
        for (int k = 0; k < K; k++) {
            const int4 off = prm[sl].off[k];  // broadcast LDS.128
            const char* tb = (k == 0) ? tb0 : (k == 1) ? tb1 : (k == 2) ? tb2 : tb3;
            const float w0 = (k == 0) ? W0.x : (k == 1) ? W0.y : (k == 2) ? W0.z : W0.w;
            const float w1 = (k == 0) ? W1.x : (k == 1) ? W1.y : (k == 2) ? W1.z : W1.w;

            const float h0 = *reinterpret_cast<const float*>(tb + off.x);
            const float h1 = *reinterpret_cast<const float*>(tb + off.y);
            const float h2 = *reinterpret_cast<const float*>(tb + off.z);
            const float h3 = *reinterpret_cast<const float*>(tb + off.w);
            const float h4 = *reinterpret_cast<const float*>(tb + off.x + 4); // f(r+4)=f(r)+1 word

            a0 = fmaf(w0, h0, fmaf(w1, h1, a0));
            a1 = fmaf(w0, h1, fmaf(w1, h2, a1));
            a2 = fmaf(w0, h2, fmaf(w1, h3, a2));
            a3 = fmaf(w0, h3, fmaf(w1, h4, a3));
        }

        *reinterpret_cast<float4*>(op) = make_float4(a0, a1, a2, a3);
        op += C;
    }
}

extern "C" void kernel_launch(void* const* d_in, const int* in_sizes, int n_in,
                              void* d_out, int out_size) {
    // metadata order: inputs (unused), components, contributions, shift
    const float* comp    = (const float*)d_in[1];
    const float* contrib = (const float*)d_in[2];
    const float* shift   = (const float*)d_in[3];
    float*       out     = (float*)d_out;

    dim3 grid(C / BLKCH, S / SCHUNK);   // (4, 256) = 1024 blocks
    smf_kernel<<<grid, 256>>>(comp, contrib, shift, out);
}

// round 7
// speedup vs baseline: 1.3662x; 1.0019x over previous
#include <cuda_runtime.h>

#define S 2048
#define C 4096
#define K 4
#define SCHUNK 8            // samples per block
#define BLKCH 1024          // channels per block (8 warps * 128)
#define NW 8                // warps per block
#define SUBW 36             // de-interleave sub-array stride (words) per k
#define KW (4 * SUBW)       // words per k per warp tile (144)
#define WTILE (K * KW)      // words per warp tile (576)

// Warp-private per-sample params.
struct WParams {
    float4 w0[SCHUNK];         // tap0 weight per k
    float4 w1[SCHUNK];         // tap1 weight per k
    int4   off[SCHUNK][K];     // byte offsets f(r+j)*4, j=0..3 (j=4 is off.x+4)
};

// Fully warp-autonomous: each warp stages its own 128-channel (+halo) tile and
// its own params into warp-private smem; only __syncwarp needed. Tap word
// 4*lane + x (x in [0,11]) lives at (x&3)*SUBW + (x>>2) + lane: lane-consecutive
// LDS (conflict-free) with a sample-uniform precomputed byte offset, and
// f(x+4) = f(x)+1 word.
__global__ void __launch_bounds__(256, 8)
smf_kernel(const float* __restrict__ comp,      // (K, C)
           const float* __restrict__ contrib,   // (S, K)
           const float* __restrict__ shift,     // (S, K)
           float* __restrict__ out)             // (S, C)
{
    __shared__ float   s_tile[NW][WTILE];
    __shared__ WParams s_prm[NW];

    const int tid  = threadIdx.x;
    const int warp = tid >> 5;
    const int lane = tid & 31;
    const int wc0  = blockIdx.x * BLKCH + warp * 128;   // warp's first channel
    const int s0   = blockIdx.y * SCHUNK;

    // ---- param compute: lane l handles (sample l>>2, comp l&3) ----
    {
        const int sl = lane >> 2;
        const int kk = lane & 3;
        const float sh = __ldg(&shift[(s0 + sl) * K + kk]);
        const float w  = __ldg(&contrib[(s0 + sl) * K + kk]);
        const float m  = floorf(sh);
        const float f  = sh - m;
        int r = (int)m + 4;                    // shift in [-4,4) -> r in [0,7]
        r = max(0, min(7, r));
        const float w1 = w * f;
        reinterpret_cast<float*>(&s_prm[warp].w0[sl])[kk] = w - w1;
        reinterpret_cast<float*>(&s_prm[warp].w1[sl])[kk] = w1;
        int o[4];
#pragma unroll
        for (int j = 0; j < 4; j++) {
            const int x = r + j;
            o[j] = ((x & 3) * SUBW + (x >> 2)) * 4;    // byte offset
        }
        s_prm[warp].off[sl][kk] = make_int4(o[0], o[1], o[2], o[3]);
    }

    // ---- stage warp-private tile: 140 words per k (channels wc0-4 .. wc0+135) ----
    float* wt = s_tile[warp];
#pragma unroll
    for (int k = 0; k < K; k++) {
#pragma unroll
        for (int i = 0; i < 5; i++) {
            if (i < 4 || lane < 12) {               // 140 = 4*32 + 12
                const int t = lane + i * 32;
                const int g = wc0 - 4 + t;
                const float v = (g >= 0 && g < C) ? __ldg(&comp[k * C + g]) : 0.f;
                wt[k * KW + (t & 3) * SUBW + (t >> 2)] = v;
            }
        }
    }
    __syncwarp();

    // per-k tap base pointers (byte-addressed)
    const char* tb0 = reinterpret_cast<const char*>(&wt[0 * KW + lane]);
    const char* tb1 = reinterpret_cast<const char*>(&wt[1 * KW + lane]);
    const char* tb2 = reinterpret_cast<const char*>(&wt[2 * KW + lane]);
    const char* tb3 = reinterpret_cast<const char*>(&wt[3 * KW + lane]);

    float* op = out + (size_t)s0 * C + wc0 + 4 * lane;

#pragma unroll 2
    for (int sl = 0; sl < SCHUNK; sl++) {
        const float4 W0 = s_prm[warp].w0[sl];      // broadcast LDS.128
        const float4 W1 = s_prm[warp].w1[sl];

        float a0 = 0.f, a1 = 0.f, a2 = 0.f, a3 = 0.f;

#pragma unroll
        for (int k = 0; k < K; k++) {
            const int4 off = s_prm[warp].off[sl][k];   // broadcast LDS.128
            const char* tb = (k == 0) ? tb0 : (k == 1) ? tb1 : (k == 2) ? tb2 : tb3;
            const float w0 = (k == 0) ? W0.x : (k == 1) ? W0.y : (k == 2) ? W0.z : W0.w;
            const float w1 = (k == 0) ? W1.x : (k == 1) ? W1.y : (k == 2) ? W1.z : W1.w;

            const float h0 = *reinterpret_cast<const float*>(tb + off.x);
            const float h1 = *reinterpret_cast<const float*>(tb + off.y);
            const float h2 = *reinterpret_cast<const float*>(tb + off.z);
            const float h3 = *reinterpret_cast<const float*>(tb + off.w);
            const float h4 = *reinterpret_cast<const float*>(tb + off.x + 4); // f(r+4)=f(r)+1

            a0 = fmaf(w0, h0, fmaf(w1, h1, a0));
            a1 = fmaf(w0, h1, fmaf(w1, h2, a1));
            a2 = fmaf(w0, h2, fmaf(w1, h3, a2));
            a3 = fmaf(w0, h3, fmaf(w1, h4, a3));
        }

        *reinterpret_cast<float4*>(op) = make_float4(a0, a1, a2, a3);
        op += C;
    }
}

extern "C" void kernel_launch(void* const* d_in, const int* in_sizes, int n_in,
                              void* d_out, int out_size) {
    // metadata order: inputs (unused), components, contributions, shift
    const float* comp    = (const float*)d_in[1];
    const float* contrib = (const float*)d_in[2];
    const float* shift   = (const float*)d_in[3];
    float*       out     = (float*)d_out;

    // Allow 8 CTAs/SM worth of smem (24 KB * 8 = 192 KB): max carveout.
    static bool configured = false;
    if (!configured) {
        cudaFuncSetAttribute(smf_kernel,
                             cudaFuncAttributePreferredSharedMemoryCarveout, 100);
        configured = true;
    }

    dim3 grid(C / BLKCH, S / SCHUNK);   // (4, 256) = 1024 blocks
    smf_kernel<<<grid, 256>>>(comp, contrib, shift, out);
}